// round 11
// baseline (speedup 1.0000x reference)
#include <cuda_runtime.h>
#include <cuda_bf16.h>

// RPDC depthwise 5x5 conv via 8 taps of a 3x3 weight.
// x: (16,256,128,128) f32 -> out same shape. DRAM-bound.
//
// R11 restructure: output-accumulator ring instead of input-row window.
// Each input row r is expanded (shuffle halo) once and scattered into the
// 5 pending output accumulators (roles k=0..4). Live state: 5 float4 accs
// + transient row + lookahead ~= 50 regs, so launch_bounds(256,5) raises
// occupancy to 40 warps/SM WITHOUT serializing the lookahead loads (the
// failure mode of R6/R7, where the 40-float window couldn't fit in 48 regs).
//
// Tap roles for output y (cross-correlation):
//   row y-2 (k=0): +t0*e[j]   +t1*e[j+2] +t2*e[j+4]
//   row y-1 (k=1): -t0*e[j+1] -t1*e[j+2] -t2*e[j+3]
//   row y   (k=2): +t3*(e[j]-e[j+1]) +t4*(e[j+4]-e[j+3])
//   row y+1 (k=3): -t5*e[j+1] -t6*e[j+2] -t7*e[j+3]
//   row y+2 (k=4): +t5*e[j]   +t6*e[j+2] +t7*e[j+4]   -> store

#define W_DIM 128
#define H_DIM 128
#define TILE_H 32

__device__ __forceinline__ float4 ldrow(const float* __restrict__ xp, int gy, int lane) {
    if ((unsigned)gy < (unsigned)H_DIM)
        return __ldg(((const float4*)xp) + gy * (W_DIM / 4) + lane);
    return make_float4(0.f, 0.f, 0.f, 0.f);
}

// Expand lane's float4 (cols 4L..4L+3) into 8-float window (cols 4L-2..4L+5)
// via neighbor-lane shuffles. Lane 0 / 31 edges are zero padding.
#define EXPAND(dst, v)                                                  \
    {                                                                   \
        float _lz = __shfl_up_sync(0xffffffffu, (v).z, 1);              \
        float _lw = __shfl_up_sync(0xffffffffu, (v).w, 1);              \
        float _rx = __shfl_down_sync(0xffffffffu, (v).x, 1);            \
        float _ry = __shfl_down_sync(0xffffffffu, (v).y, 1);            \
        (dst)[0] = lane0 ? 0.f : _lz;                                   \
        (dst)[1] = lane0 ? 0.f : _lw;                                   \
        (dst)[2] = (v).x; (dst)[3] = (v).y;                             \
        (dst)[4] = (v).z; (dst)[5] = (v).w;                             \
        (dst)[6] = lane31 ? 0.f : _rx;                                  \
        (dst)[7] = lane31 ? 0.f : _ry;                                  \
    }

__global__ __launch_bounds__(256, 5) void rpdc_kernel(
    const float* __restrict__ x,
    const float* __restrict__ w,
    float* __restrict__ out)
{
    const int lane = threadIdx.x & 31;
    const int warp = threadIdx.x >> 5;
    const int item = blockIdx.x * 8 + warp;       // 0..16383
    const int plane = item >> 2;                  // n*256 + c
    const int y0 = (item & 3) * TILE_H;
    const int c = plane & 255;

    const float* xp = x + (size_t)plane * (H_DIM * W_DIM);
    float*       op = out + (size_t)plane * (H_DIM * W_DIM);

    const float* wp = w + c * 9;
    const float t0 = wp[1], t1 = wp[2], t2 = wp[3], t3 = wp[4];
    const float t4 = wp[5], t5 = wp[6], t6 = wp[7], t7 = wp[8];
    const float n0 = -t0, n1 = -t1, n2 = -t2;
    const float n5 = -t5, n6 = -t6, n7 = -t7;

    const bool lane0  = (lane == 0);
    const bool lane31 = (lane == 31);

    // Ring of 5 output accumulators; acc[y % 5] accumulates output row y.
    float acc[5][4];

    // Lookahead: rows y0-2, y0-1 preloaded.
    float4 nxt  = ldrow(xp, y0 - 2, lane);
    float4 nxt2 = ldrow(xp, y0 - 1, lane);

    // Input rows r = y0-2 .. y0+TILE_H+1  (rr = 0 .. TILE_H+3), fully unrolled.
    #pragma unroll
    for (int rr = 0; rr < TILE_H + 4; ++rr) {
        float4 cur = nxt;
        nxt = nxt2;
        nxt2 = ldrow(xp, y0 + rr, lane);          // 2-deep lookahead

        float e[8];
        EXPAND(e, cur);

        // k=0: init accumulator for output o=rr (first touch).
        if (rr < TILE_H) {
            float* A = acc[rr % 5];
            #pragma unroll
            for (int j = 0; j < 4; ++j)
                A[j] = t0 * e[j] + t1 * e[j + 2] + t2 * e[j + 4];
        }
        // k=1: output o=rr-1.
        if (rr >= 1 && rr - 1 < TILE_H) {
            float* A = acc[(rr - 1) % 5];
            #pragma unroll
            for (int j = 0; j < 4; ++j)
                A[j] = fmaf(n0, e[j + 1], fmaf(n1, e[j + 2], fmaf(n2, e[j + 3], A[j])));
        }
        // k=2: output o=rr-2.
        if (rr >= 2 && rr - 2 < TILE_H) {
            float* A = acc[(rr - 2) % 5];
            #pragma unroll
            for (int j = 0; j < 4; ++j)
                A[j] = fmaf(t3, e[j] - e[j + 1], fmaf(t4, e[j + 4] - e[j + 3], A[j]));
        }
        // k=3: output o=rr-3.
        if (rr >= 3 && rr - 3 < TILE_H) {
            float* A = acc[(rr - 3) % 5];
            #pragma unroll
            for (int j = 0; j < 4; ++j)
                A[j] = fmaf(n5, e[j + 1], fmaf(n6, e[j + 2], fmaf(n7, e[j + 3], A[j])));
        }
        // k=4: output o=rr-4 completes -> store.
        if (rr >= 4) {
            const int o = rr - 4;
            float* A = acc[o % 5];
            float4 ov;
            #pragma unroll
            for (int j = 0; j < 4; ++j)
                ((float*)&ov)[j] = fmaf(t5, e[j], fmaf(t6, e[j + 2], fmaf(t7, e[j + 4], A[j])));
            __stcs(((float4*)op) + (y0 + o) * (W_DIM / 4) + lane, ov);
        }
    }
}

extern "C" void kernel_launch(void* const* d_in, const int* in_sizes, int n_in,
                              void* d_out, int out_size)
{
    const float* x = (const float*)d_in[0];   // 16*256*128*128
    const float* w = (const float*)d_in[1];   // 256*1*3*3
    float* out = (float*)d_out;

    // 4096 planes * 4 row-tiles = 16384 warps / 8 warps per block
    dim3 grid(16 * 256 * 4 / 8);
    rpdc_kernel<<<grid, 256>>>(x, w, out);
}

// round 12
// speedup vs baseline: 1.1253x; 1.1253x over previous
#include <cuda_runtime.h>
#include <cuda_bf16.h>

// RPDC depthwise 5x5 conv via 8 taps of a 3x3 weight.
// x: (16,256,128,128) f32 -> out same shape.
//
// FINAL (R8, best measured 88.16us; kernel 81us, 6.2TB/s = HBM mixed-r/w
// ceiling for this streaming pattern):
//  - one warp per (plane, 32-row strip); lane holds 4 columns (float4)
//  - vertical 5-row window in registers, fully unrolled (renaming, no MOVs)
//  - horizontal +/-2 halo via warp shuffles (no smem; L1 ~38%)
//  - 3-deep global-load lookahead (per-warp MLP covers DRAM latency)
//  - streaming stores (__stcs): output never re-read
//  - __launch_bounds__(256,4) pins 64 regs: every 48-reg variant tested
//    (R6/R7/R9/R11) lost ~10% DRAM throughput to serialized loads,
//    regardless of occupancy gains.

#define W_DIM 128
#define H_DIM 128
#define TILE_H 32

__device__ __forceinline__ float4 ldrow(const float* __restrict__ xp, int gy, int lane) {
    if ((unsigned)gy < (unsigned)H_DIM)
        return __ldg(((const float4*)xp) + gy * (W_DIM / 4) + lane);
    return make_float4(0.f, 0.f, 0.f, 0.f);
}

// Expand lane's float4 (cols 4L..4L+3) into 8-float window (cols 4L-2..4L+5)
// via neighbor-lane shuffles. Lane 0 / 31 edges are zero padding.
#define EXPAND(dst, v)                                                  \
    {                                                                   \
        float _lz = __shfl_up_sync(0xffffffffu, (v).z, 1);              \
        float _lw = __shfl_up_sync(0xffffffffu, (v).w, 1);              \
        float _rx = __shfl_down_sync(0xffffffffu, (v).x, 1);            \
        float _ry = __shfl_down_sync(0xffffffffu, (v).y, 1);            \
        (dst)[0] = lane0 ? 0.f : _lz;                                   \
        (dst)[1] = lane0 ? 0.f : _lw;                                   \
        (dst)[2] = (v).x; (dst)[3] = (v).y;                             \
        (dst)[4] = (v).z; (dst)[5] = (v).w;                             \
        (dst)[6] = lane31 ? 0.f : _rx;                                  \
        (dst)[7] = lane31 ? 0.f : _ry;                                  \
    }

__global__ __launch_bounds__(256, 4) void rpdc_kernel(
    const float* __restrict__ x,
    const float* __restrict__ w,
    float* __restrict__ out)
{
    const int lane = threadIdx.x & 31;
    const int warp = threadIdx.x >> 5;
    const int item = blockIdx.x * 8 + warp;       // 0..16383
    const int plane = item >> 2;                  // n*256 + c
    const int y0 = (item & 3) * TILE_H;
    const int c = plane & 255;

    const float* xp = x + (size_t)plane * (H_DIM * W_DIM);
    float*       op = out + (size_t)plane * (H_DIM * W_DIM);

    const float* wp = w + c * 9;
    const float t0 = wp[1], t1 = wp[2], t2 = wp[3], t3 = wp[4];
    const float t4 = wp[5], t5 = wp[6], t6 = wp[7], t7 = wp[8];

    const bool lane0  = (lane == 0);
    const bool lane31 = (lane == 31);

    // a[k][j+2] = input col (4*lane + j), j in -2..5, window row k (y-2+k).
    float a[5][8];

    // Prologue: rows y0-2 .. y0+1 -> a[0..3]; lookahead rows y0+2..y0+4.
    #pragma unroll
    for (int k = 0; k < 4; ++k) {
        float4 v = ldrow(xp, y0 + k - 2, lane);
        EXPAND(a[k], v);
    }
    float4 nxt  = ldrow(xp, y0 + 2, lane);
    float4 nxt2 = ldrow(xp, y0 + 3, lane);
    float4 nxt3 = ldrow(xp, y0 + 4, lane);

    #pragma unroll
    for (int y = 0; y < TILE_H; ++y) {
        float4 cur = nxt;
        nxt = nxt2;
        nxt2 = nxt3;
        nxt3 = ldrow(xp, y0 + y + 5, lane);   // 3-deep lookahead
        EXPAND(a[4], cur);

        float4 o;
        #pragma unroll
        for (int j = 0; j < 4; ++j) {
            float acc;
            acc  = t0 * (a[0][j]     - a[1][j + 1]);
            acc += t1 * (a[0][j + 2] - a[1][j + 2]);
            acc += t2 * (a[0][j + 4] - a[1][j + 3]);
            acc += t3 * (a[2][j]     - a[2][j + 1]);
            acc += t4 * (a[2][j + 4] - a[2][j + 3]);
            acc += t5 * (a[4][j]     - a[3][j + 1]);
            acc += t6 * (a[4][j + 2] - a[3][j + 2]);
            acc += t7 * (a[4][j + 4] - a[3][j + 3]);
            ((float*)&o)[j] = acc;
        }
        // Streaming store: output never re-read; evict-first in L2.
        __stcs(((float4*)op) + (y0 + y) * (W_DIM / 4) + lane, o);

        // Roll window — fully unrolled, becomes register renaming.
        #pragma unroll
        for (int k = 0; k < 4; ++k)
            #pragma unroll
            for (int cc = 0; cc < 8; ++cc)
                a[k][cc] = a[k + 1][cc];
    }
}

extern "C" void kernel_launch(void* const* d_in, const int* in_sizes, int n_in,
                              void* d_out, int out_size)
{
    const float* x = (const float*)d_in[0];   // 16*256*128*128
    const float* w = (const float*)d_in[1];   // 256*1*3*3
    float* out = (float*)d_out;

    // 4096 planes * 4 row-tiles = 16384 warps / 8 warps per block
    dim3 grid(16 * 256 * 4 / 8);
    rpdc_kernel<<<grid, 256>>>(x, w, out);
}

// round 13
// speedup vs baseline: 1.1383x; 1.0116x over previous
#include <cuda_runtime.h>
#include <cuda_bf16.h>

// RPDC depthwise 5x5 conv via 8 taps of a 3x3 weight.
// x: (16,256,128,128) f32 -> out same shape.
//
// FINAL — converged at the mixed-r/w HBM ceiling (~6.2 TB/s, 78% of spec;
// kernel ~81us, bench ~88us incl. fixed harness overhead).
//
// Design (validated over 12 rounds):
//  - one warp per (plane, 32-row strip); lane holds 4 columns (float4)
//  - vertical 5-row window in registers, fully unrolled (renaming, no MOVs)
//  - horizontal +/-2 halo via warp shuffles (no smem; L1 ~38%)
//  - 3-deep global-load lookahead (per-warp MLP covers DRAM latency)
//  - streaming stores (__stcs): output never re-read
//  - __launch_bounds__(256,4) pins 64 regs: every 48-reg variant tested
//    (R6/R7/R9/R11) lost ~10% DRAM throughput to ptxas scheduling loads
//    next to their uses, regardless of occupancy gains.

#define W_DIM 128
#define H_DIM 128
#define TILE_H 32

__device__ __forceinline__ float4 ldrow(const float* __restrict__ xp, int gy, int lane) {
    if ((unsigned)gy < (unsigned)H_DIM)
        return __ldg(((const float4*)xp) + gy * (W_DIM / 4) + lane);
    return make_float4(0.f, 0.f, 0.f, 0.f);
}

// Expand lane's float4 (cols 4L..4L+3) into 8-float window (cols 4L-2..4L+5)
// via neighbor-lane shuffles. Lane 0 / 31 edges are zero padding.
#define EXPAND(dst, v)                                                  \
    {                                                                   \
        float _lz = __shfl_up_sync(0xffffffffu, (v).z, 1);              \
        float _lw = __shfl_up_sync(0xffffffffu, (v).w, 1);              \
        float _rx = __shfl_down_sync(0xffffffffu, (v).x, 1);            \
        float _ry = __shfl_down_sync(0xffffffffu, (v).y, 1);            \
        (dst)[0] = lane0 ? 0.f : _lz;                                   \
        (dst)[1] = lane0 ? 0.f : _lw;                                   \
        (dst)[2] = (v).x; (dst)[3] = (v).y;                             \
        (dst)[4] = (v).z; (dst)[5] = (v).w;                             \
        (dst)[6] = lane31 ? 0.f : _rx;                                  \
        (dst)[7] = lane31 ? 0.f : _ry;                                  \
    }

__global__ __launch_bounds__(256, 4) void rpdc_kernel(
    const float* __restrict__ x,
    const float* __restrict__ w,
    float* __restrict__ out)
{
    const int lane = threadIdx.x & 31;
    const int warp = threadIdx.x >> 5;
    const int item = blockIdx.x * 8 + warp;       // 0..16383
    const int plane = item >> 2;                  // n*256 + c
    const int y0 = (item & 3) * TILE_H;
    const int c = plane & 255;

    const float* xp = x + (size_t)plane * (H_DIM * W_DIM);
    float*       op = out + (size_t)plane * (H_DIM * W_DIM);

    const float* wp = w + c * 9;
    const float t0 = wp[1], t1 = wp[2], t2 = wp[3], t3 = wp[4];
    const float t4 = wp[5], t5 = wp[6], t6 = wp[7], t7 = wp[8];

    const bool lane0  = (lane == 0);
    const bool lane31 = (lane == 31);

    // a[k][j+2] = input col (4*lane + j), j in -2..5, window row k (y-2+k).
    float a[5][8];

    // Prologue: rows y0-2 .. y0+1 -> a[0..3]; lookahead rows y0+2..y0+4.
    #pragma unroll
    for (int k = 0; k < 4; ++k) {
        float4 v = ldrow(xp, y0 + k - 2, lane);
        EXPAND(a[k], v);
    }
    float4 nxt  = ldrow(xp, y0 + 2, lane);
    float4 nxt2 = ldrow(xp, y0 + 3, lane);
    float4 nxt3 = ldrow(xp, y0 + 4, lane);

    #pragma unroll
    for (int y = 0; y < TILE_H; ++y) {
        float4 cur = nxt;
        nxt = nxt2;
        nxt2 = nxt3;
        nxt3 = ldrow(xp, y0 + y + 5, lane);   // 3-deep lookahead
        EXPAND(a[4], cur);

        float4 o;
        #pragma unroll
        for (int j = 0; j < 4; ++j) {
            float acc;
            acc  = t0 * (a[0][j]     - a[1][j + 1]);
            acc += t1 * (a[0][j + 2] - a[1][j + 2]);
            acc += t2 * (a[0][j + 4] - a[1][j + 3]);
            acc += t3 * (a[2][j]     - a[2][j + 1]);
            acc += t4 * (a[2][j + 4] - a[2][j + 3]);
            acc += t5 * (a[4][j]     - a[3][j + 1]);
            acc += t6 * (a[4][j + 2] - a[3][j + 2]);
            acc += t7 * (a[4][j + 4] - a[3][j + 3]);
            ((float*)&o)[j] = acc;
        }
        // Streaming store: output never re-read; evict-first in L2.
        __stcs(((float4*)op) + (y0 + y) * (W_DIM / 4) + lane, o);

        // Roll window — fully unrolled, becomes register renaming.
        #pragma unroll
        for (int k = 0; k < 4; ++k)
            #pragma unroll
            for (int cc = 0; cc < 8; ++cc)
                a[k][cc] = a[k + 1][cc];
    }
}

extern "C" void kernel_launch(void* const* d_in, const int* in_sizes, int n_in,
                              void* d_out, int out_size)
{
    const float* x = (const float*)d_in[0];   // 16*256*128*128
    const float* w = (const float*)d_in[1];   // 256*1*3*3
    float* out = (float*)d_out;

    // 4096 planes * 4 row-tiles = 16384 warps / 8 warps per block
    dim3 grid(16 * 256 * 4 / 8);
    rpdc_kernel<<<grid, 256>>>(x, w, out);
}